// round 1
// baseline (speedup 1.0000x reference)
#include <cuda_runtime.h>
#include <cuda_fp16.h>
#include <cstdint>

// ---------------- problem constants ----------------
#define NUM_CTAS 148
#define NTHREADS 512
#define NWARPS   (NTHREADS / 32)
#define HDIM     2048
#define EDIM     1024
#define USMEM    13                      // hidden units whose W_hh rows live in smem, per CTA
#define USMEM_TOT (NUM_CTAS * USMEM)     // 1924
#define UL2      (HDIM - USMEM_TOT)      // 124 overflow units, W_hh rows read from L2 (fp16)
#define MAXT     2048

#define SMEM_W_HALFS (4 * USMEM * HDIM)          // 52 rows * 2048 halfs
#define SMEM_W_BYTES (SMEM_W_HALFS * 2)          // 212992
#define SMEM_TOTAL   (SMEM_W_BYTES + HDIM * 4 + (4 * 56 + 8) * 4)  // + h stage + small arrays

// ---------------- device globals (no allocations allowed) ----------------
__device__ __half   g_whh_l2[(size_t)UL2 * 4 * HDIM];  // fp16 copy of overflow W_hh rows (~2MB)
__device__ float    g_h[2][HDIM];                      // double-buffered hidden state
__device__ float    g_rawacc[2 * MAXT];                // per-step W_out@h accumulators
__device__ unsigned g_bar_cnt;                         // grid barrier state (0-init, restored)
__device__ unsigned g_bar_gen;

// ---------------- helpers ----------------
__device__ __forceinline__ unsigned ld_acq_u32(const unsigned* p) {
    unsigned v;
    asm volatile("ld.acquire.gpu.u32 %0, [%1];" : "=r"(v) : "l"(p));
    return v;
}
__device__ __forceinline__ float ldcg_f(const float* p) {
    float v;
    asm volatile("ld.global.cg.f32 %0, [%1];" : "=f"(v) : "l"(p));
    return v;
}
__device__ __forceinline__ float4 ldcg_f4(const float4* p) {
    float4 v;
    asm volatile("ld.global.cg.v4.f32 {%0,%1,%2,%3}, [%4];"
                 : "=f"(v.x), "=f"(v.y), "=f"(v.z), "=f"(v.w) : "l"(p));
    return v;
}
__device__ __forceinline__ uint4 ldcg_u4(const uint4* p) {
    uint4 v;
    asm volatile("ld.global.cg.v4.u32 {%0,%1,%2,%3}, [%4];"
                 : "=r"(v.x), "=r"(v.y), "=r"(v.z), "=r"(v.w) : "l"(p));
    return v;
}

// Sense-reversal grid barrier in L2. All CTAs execute the same count.
__device__ __forceinline__ void grid_barrier() {
    __syncthreads();
    if (threadIdx.x == 0) {
        __threadfence();
        unsigned g = ld_acq_u32(&g_bar_gen);
        if (atomicAdd(&g_bar_cnt, 1u) == gridDim.x - 1u) {
            g_bar_cnt = 0u;          // all arrived; safe plain store
            __threadfence();
            atomicAdd(&g_bar_gen, 1u);
        } else {
            while (ld_acq_u32(&g_bar_gen) == g) { }
        }
    }
    __syncthreads();
}

// ---------------- kernel ----------------
__global__ void __launch_bounds__(NTHREADS, 1)
lstm_decoder_kernel(const float* __restrict__ h0, const float* __restrict__ c0,
                    const float* __restrict__ gtruth, const int* __restrict__ use_gt,
                    const float* __restrict__ W_emb, const float* __restrict__ b_emb,
                    const float* __restrict__ W_ih, const float* __restrict__ b_ih,
                    const float* __restrict__ W_hh, const float* __restrict__ b_hh,
                    const float* __restrict__ W_out, const float* __restrict__ b_out,
                    const int* __restrict__ out_len_ptr, float* __restrict__ out)
{
    const int cta  = blockIdx.x;
    const int tid  = threadIdx.x;
    const int lane = tid & 31;
    const int warp = tid >> 5;
    const int nu   = USMEM + (cta < UL2 ? 1 : 0);   // units handled by this CTA
    const int nrows = 4 * nu;                        // gate rows (i,f,g,o per unit)

    int T = MAXT;
    if (out_len_ptr) { int t = *out_len_ptr; if (t > 0 && t <= MAXT) T = t; }

    extern __shared__ __align__(16) char sm[];
    __half* w_s = (__half*)sm;                              // 52 rows * 2048 fp16 weights
    float*  h_s = (float*)(sm + SMEM_W_BYTES);              // staged h (2048 fp32)
    float*  A0  = (float*)(sm + SMEM_W_BYTES + HDIM * 4);   // 56
    float*  A1  = A0 + 56;                                  // 56
    float*  DD  = A1 + 56;                                  // 56 (fused bias)
    float*  GA  = DD + 56;                                  // 56 (gate values)
    float*  VW  = GA + 56;                                  // [v0, v1, wacc0, wacc1]

    // ---- Prologue 1: convert this CTA's W_hh rows (13 smem units) fp32 -> fp16 smem ----
    for (int r = 0; r < 4 * USMEM; r++) {                   // r = g*13+u
        int g = r / USMEM, u = r - g * USMEM;
        int grow = g * HDIM + (USMEM * cta + u);
        const float4* src = (const float4*)(W_hh + (size_t)grow * HDIM);
        float4 v = src[tid];                                // 512 threads * 4 = 2048
        __half2* dst = (__half2*)(w_s + (size_t)r * HDIM);
        dst[2 * tid]     = __floats2half2_rn(v.x, v.y);
        dst[2 * tid + 1] = __floats2half2_rn(v.z, v.w);
    }
    // ---- Prologue 2: convert overflow unit's 4 rows into the global fp16 buffer ----
    if (cta < UL2) {
        for (int g = 0; g < 4; g++) {
            int grow = g * HDIM + (USMEM_TOT + cta);
            const float4* src = (const float4*)(W_hh + (size_t)grow * HDIM);
            float4 v = src[tid];
            __half2* dst = (__half2*)(g_whh_l2 + ((size_t)(cta * 4 + g)) * HDIM);
            dst[2 * tid]     = __floats2half2_rn(v.x, v.y);
            dst[2 * tid + 1] = __floats2half2_rn(v.z, v.w);
        }
    }
    // ---- Prologue 3: A = W_ih@W_emb (per row), fused bias d = W_ih@b_emb + b_ih + b_hh ----
    for (int r = warp; r < nrows; r += NWARPS) {
        int g = r / nu, u = r - g * nu;
        int gu   = (u < USMEM) ? (USMEM * cta + u) : (USMEM_TOT + cta);
        int grow = g * HDIM + gu;
        const float* wr = W_ih + (size_t)grow * EDIM;
        float a0 = 0.f, a1 = 0.f, dd = 0.f;
        for (int k = lane; k < EDIM; k += 32) {
            float w = wr[k];
            a0 += w * W_emb[2 * k];
            a1 += w * W_emb[2 * k + 1];
            dd += w * b_emb[k];
        }
        #pragma unroll
        for (int off = 16; off; off >>= 1) {
            a0 += __shfl_xor_sync(0xffffffffu, a0, off);
            a1 += __shfl_xor_sync(0xffffffffu, a1, off);
            dd += __shfl_xor_sync(0xffffffffu, dd, off);
        }
        if (lane == 0) { A0[r] = a0; A1[r] = a1; DD[r] = dd + b_ih[grow] + b_hh[grow]; }
    }
    // ---- Prologue 4: init h, c, W_out regs; zero raw accumulators ----
    float c_reg = 0.f, wo0 = 0.f, wo1 = 0.f;
    int   my_gu = -1;
    if (tid < nu) {
        my_gu = (tid < USMEM) ? (USMEM * cta + tid) : (USMEM_TOT + cta);
        c_reg = c0[my_gu];
        g_h[0][my_gu] = h0[my_gu];
        wo0 = W_out[my_gu];
        wo1 = W_out[HDIM + my_gu];
    }
    {
        int idx = cta * NTHREADS + tid;
        if (idx < 2 * MAXT) g_rawacc[idx] = 0.f;
    }
    const float b_o0 = b_out[0], b_o1 = b_out[1];
    float loss = 0.f;
    if (tid == 0) { VW[0] = 1.f; VW[1] = 1.f; VW[2] = 0.f; VW[3] = 0.f; } // v_0 = (1,1)
    __threadfence();
    grid_barrier();

    // =============== main recurrence ===============
    for (int t = 0; t < T; t++) {
        // Phase A: finish step t-1 (raw, teacher forcing, preds/loss), stage h
        if (t > 0 && tid == 0) {
            float r0 = ldcg_f(&g_rawacc[2 * (t - 1)])     + b_o0;
            float r1 = ldcg_f(&g_rawacc[2 * (t - 1) + 1]) + b_o1;
            float gt0 = gtruth[2 * (t - 1)], gt1 = gtruth[2 * (t - 1) + 1];
            int ug = use_gt[t - 1];
            VW[0] = (ug == 1) ? gt0 : r0;
            VW[1] = (ug == 1) ? gt1 : r1;
            VW[2] = 0.f; VW[3] = 0.f;
            if (cta == 0) {
                out[2 * (t - 1)] = r0; out[2 * (t - 1) + 1] = r1;
                float d0 = r0 - gt0, d1 = r1 - gt1;
                loss += 0.5f * (d0 * d0 + d1 * d1);
            }
        }
        {
            const float4* hb = (const float4*)(g_h[t & 1]);
            ((float4*)h_s)[tid] = ldcg_f4(hb + tid);
        }
        __syncthreads();

        const float v0s = VW[0], v1s = VW[1];

        // load h fragment: lane covers cols {256k + 8*lane + j}
        float hf[64];
        {
            const float4* h4 = (const float4*)h_s;
            #pragma unroll
            for (int k = 0; k < 8; k++) {
                float4 x = h4[64 * k + 2 * lane];
                float4 y = h4[64 * k + 2 * lane + 1];
                hf[8 * k + 0] = x.x; hf[8 * k + 1] = x.y; hf[8 * k + 2] = x.z; hf[8 * k + 3] = x.w;
                hf[8 * k + 4] = y.x; hf[8 * k + 5] = y.y; hf[8 * k + 6] = y.z; hf[8 * k + 7] = y.w;
            }
        }

        // Phase B: gate rows (warp-per-row, fp16 weights, fp32 accumulate)
        for (int r = warp; r < nrows; r += NWARPS) {
            int g = r / nu, u = r - g * nu;
            float acc0 = 0.f, acc1 = 0.f, acc2 = 0.f, acc3 = 0.f;
            if (u < USMEM) {
                const uint4* wrow = (const uint4*)(w_s + (size_t)(g * USMEM + u) * HDIM);
                #pragma unroll
                for (int k = 0; k < 8; k++) {
                    uint4 w8 = wrow[32 * k + lane];
                    __half2* hw = (__half2*)&w8;
                    float2 f0 = __half22float2(hw[0]);
                    float2 f1 = __half22float2(hw[1]);
                    float2 f2 = __half22float2(hw[2]);
                    float2 f3 = __half22float2(hw[3]);
                    acc0 = fmaf(f0.x, hf[8 * k + 0], acc0); acc1 = fmaf(f0.y, hf[8 * k + 1], acc1);
                    acc2 = fmaf(f1.x, hf[8 * k + 2], acc2); acc3 = fmaf(f1.y, hf[8 * k + 3], acc3);
                    acc0 = fmaf(f2.x, hf[8 * k + 4], acc0); acc1 = fmaf(f2.y, hf[8 * k + 5], acc1);
                    acc2 = fmaf(f3.x, hf[8 * k + 6], acc2); acc3 = fmaf(f3.y, hf[8 * k + 7], acc3);
                }
            } else {
                const uint4* wrow = (const uint4*)(g_whh_l2 + (size_t)(cta * 4 + g) * HDIM);
                #pragma unroll
                for (int k = 0; k < 8; k++) {
                    uint4 w8 = ldcg_u4(wrow + 32 * k + lane);
                    __half2* hw = (__half2*)&w8;
                    float2 f0 = __half22float2(hw[0]);
                    float2 f1 = __half22float2(hw[1]);
                    float2 f2 = __half22float2(hw[2]);
                    float2 f3 = __half22float2(hw[3]);
                    acc0 = fmaf(f0.x, hf[8 * k + 0], acc0); acc1 = fmaf(f0.y, hf[8 * k + 1], acc1);
                    acc2 = fmaf(f1.x, hf[8 * k + 2], acc2); acc3 = fmaf(f1.y, hf[8 * k + 3], acc3);
                    acc0 = fmaf(f2.x, hf[8 * k + 4], acc0); acc1 = fmaf(f2.y, hf[8 * k + 5], acc1);
                    acc2 = fmaf(f3.x, hf[8 * k + 6], acc2); acc3 = fmaf(f3.y, hf[8 * k + 7], acc3);
                }
            }
            float acc = (acc0 + acc1) + (acc2 + acc3);
            #pragma unroll
            for (int off = 16; off; off >>= 1) acc += __shfl_xor_sync(0xffffffffu, acc, off);
            if (lane == 0) GA[r] = acc + A0[r] * v0s + A1[r] * v1s + DD[r];
        }
        __syncthreads();

        // Phase C: LSTM cell update for my units, h write + W_out partials
        if (tid < nu) {
            float gi = GA[tid], gf = GA[nu + tid], gg = GA[2 * nu + tid], go = GA[3 * nu + tid];
            float si = 1.0f / (1.0f + expf(-gi));
            float sf = 1.0f / (1.0f + expf(-gf));
            float so = 1.0f / (1.0f + expf(-go));
            c_reg = sf * c_reg + si * tanhf(gg);
            float hn = so * tanhf(c_reg);
            g_h[(t + 1) & 1][my_gu] = hn;
            atomicAdd(&VW[2], wo0 * hn);
            atomicAdd(&VW[3], wo1 * hn);
        }
        __syncthreads();
        if (tid == 0) {
            atomicAdd(&g_rawacc[2 * t],     VW[2]);
            atomicAdd(&g_rawacc[2 * t + 1], VW[3]);
        }
        grid_barrier();   // fences h writes + raw_acc atomics for step t
    }

    // ---- final step's output + total loss ----
    if (cta == 0 && tid == 0) {
        float r0 = ldcg_f(&g_rawacc[2 * (T - 1)])     + b_o0;
        float r1 = ldcg_f(&g_rawacc[2 * (T - 1) + 1]) + b_o1;
        out[2 * (T - 1)] = r0; out[2 * (T - 1) + 1] = r1;
        float gt0 = gtruth[2 * (T - 1)], gt1 = gtruth[2 * (T - 1) + 1];
        float d0 = r0 - gt0, d1 = r1 - gt1;
        loss += 0.5f * (d0 * d0 + d1 * d1);
        out[2 * T] = loss;
    }
}

// ---------------- launch ----------------
extern "C" void kernel_launch(void* const* d_in, const int* in_sizes, int n_in,
                              void* d_out, int out_size)
{
    const float* h0     = (const float*)d_in[0];
    const float* c0     = (const float*)d_in[1];
    const float* gtruth = (const float*)d_in[2];
    const int*   use_gt = (const int*)  d_in[3];
    const float* W_emb  = (const float*)d_in[4];
    const float* b_emb  = (const float*)d_in[5];
    const float* W_ih   = (const float*)d_in[6];
    const float* b_ih   = (const float*)d_in[7];
    const float* W_hh   = (const float*)d_in[8];
    const float* b_hh   = (const float*)d_in[9];
    const float* W_out  = (const float*)d_in[10];
    const float* b_out  = (const float*)d_in[11];
    const int*   olen   = (n_in > 12) ? (const int*)d_in[12] : nullptr;
    float* out = (float*)d_out;

    cudaFuncSetAttribute(lstm_decoder_kernel,
                         cudaFuncAttributeMaxDynamicSharedMemorySize, SMEM_TOTAL);
    lstm_decoder_kernel<<<NUM_CTAS, NTHREADS, SMEM_TOTAL>>>(
        h0, c0, gtruth, use_gt, W_emb, b_emb, W_ih, b_ih,
        W_hh, b_hh, W_out, b_out, olen, out);
}

// round 2
// speedup vs baseline: 1.3669x; 1.3669x over previous
#include <cuda_runtime.h>
#include <cuda_fp16.h>
#include <cstdint>

// ---------------- problem constants ----------------
#define NUM_CTAS 148
#define NTHREADS 512
#define NWARPS   16
#define HDIM     2048
#define EDIM     1024
#define UPC      14          // units per CTA (148*14 = 2072 >= 2048)
#define UH       12          // units handled by HMMA (48 rows = 3 m16 tiles)
#define MAXT     2048
#define WSTRIDE  4096        // bytes per smem weight row (2048 fp16)

// smem layout (bytes)
#define OFF_W    0
#define OFF_HSF  (48 * WSTRIDE)            // float h copy (8KB)
#define OFF_HS2  (OFF_HSF + HDIM * 4)      // half  h copy (4KB)
#define OFF_PART (OFF_HS2 + HDIM * 2)      // 48 rows x 4 strips floats
#define OFF_A0   (OFF_PART + 48 * 4 * 4)
#define OFF_A1   (OFF_A0 + 56 * 4)
#define OFF_DD   (OFF_A1 + 56 * 4)
#define OFF_GA   (OFF_DD + 56 * 4)
#define OFF_VW   (OFF_GA + 56 * 4)
#define SMEM_TOTAL (OFF_VW + 64)

// ---------------- device globals ----------------
__device__ __half   g_whh_l2[(size_t)NUM_CTAS * 8 * HDIM];  // fp16 overflow rows (2/CTA = 8 gate rows)
__device__ float    g_h[2][HDIM];
__device__ float    g_rawacc[2 * MAXT];
__device__ unsigned g_bar_cnt;
__device__ unsigned g_bar_gen;

// ---------------- helpers ----------------
__device__ __forceinline__ unsigned ld_acq_u32(const unsigned* p) {
    unsigned v; asm volatile("ld.acquire.gpu.u32 %0, [%1];" : "=r"(v) : "l"(p)); return v;
}
__device__ __forceinline__ float ldcg_f(const float* p) {
    float v; asm volatile("ld.global.cg.f32 %0, [%1];" : "=f"(v) : "l"(p)); return v;
}
__device__ __forceinline__ float4 ldcg_f4(const float4* p) {
    float4 v;
    asm volatile("ld.global.cg.v4.f32 {%0,%1,%2,%3}, [%4];"
                 : "=f"(v.x), "=f"(v.y), "=f"(v.z), "=f"(v.w) : "l"(p));
    return v;
}
__device__ __forceinline__ uint4 ldcg_u4(const uint4* p) {
    uint4 v;
    asm volatile("ld.global.cg.v4.u32 {%0,%1,%2,%3}, [%4];"
                 : "=r"(v.x), "=r"(v.y), "=r"(v.z), "=r"(v.w) : "l"(p));
    return v;
}
__device__ __forceinline__ float sigf(float x) {
    return 1.0f / (1.0f + __expf(-x));
}
__device__ __forceinline__ float tanhfast(float x) {
    // 1 - 2/(e^{2x}+1): exact limits at +-inf, ~1e-6 rel err
    return 1.0f - 2.0f / (__expf(2.0f * x) + 1.0f);
}

__device__ __forceinline__ void grid_barrier() {
    __syncthreads();
    if (threadIdx.x == 0) {
        __threadfence();
        unsigned g = ld_acq_u32(&g_bar_gen);
        if (atomicAdd(&g_bar_cnt, 1u) == gridDim.x - 1u) {
            g_bar_cnt = 0u;
            __threadfence();
            atomicAdd(&g_bar_gen, 1u);
        } else {
            while (ld_acq_u32(&g_bar_gen) == g) { }
        }
    }
    __syncthreads();
}

// ---------------- kernel ----------------
__global__ void __launch_bounds__(NTHREADS, 1)
lstm_decoder_kernel(const float* __restrict__ h0, const float* __restrict__ c0,
                    const float* __restrict__ gtruth, const int* __restrict__ use_gt,
                    const float* __restrict__ W_emb, const float* __restrict__ b_emb,
                    const float* __restrict__ W_ih, const float* __restrict__ b_ih,
                    const float* __restrict__ W_hh, const float* __restrict__ b_hh,
                    const float* __restrict__ W_out, const float* __restrict__ b_out,
                    const int* __restrict__ out_len_ptr, float* __restrict__ out)
{
    const int cta  = blockIdx.x;
    const int tid  = threadIdx.x;
    const int lane = tid & 31;
    const int warp = tid >> 5;

    int nu = HDIM - cta * UPC;                 // 14 (ctas 0..145), 4 (cta 146), <=0 (cta 147)
    nu = (nu < 0) ? 0 : (nu > UPC ? UPC : nu);
    const int uh = (nu < UH) ? nu : UH;        // HMMA units: 14->12, 4->4, 0->0
    const int nrows = 4 * nu;

    int T = MAXT;
    if (out_len_ptr) { int tt = *out_len_ptr; if (tt > 0 && tt <= MAXT) T = tt; }

    extern __shared__ __align__(16) char sm[];
    char*   w_s = sm + OFF_W;
    float*  h_sf = (float*)(sm + OFF_HSF);
    char*   h_s2 = sm + OFF_HS2;
    float*  part = (float*)(sm + OFF_PART);
    float*  A0   = (float*)(sm + OFF_A0);
    float*  A1   = (float*)(sm + OFF_A1);
    float*  DD   = (float*)(sm + OFF_DD);
    float*  GA   = (float*)(sm + OFF_GA);
    float*  VW   = (float*)(sm + OFF_VW);
    const uint32_t smem_u32 = (uint32_t)__cvta_generic_to_shared(sm);

    // ---- Prologue 1: HMMA weight rows -> swizzled fp16 smem (row r = u*4+g) ----
    for (int idx = tid; idx < 4 * uh * 256; idx += NTHREADS) {
        int r = idx >> 8, c = idx & 255;                 // chunk = 16B = 8 halfs
        int u = r >> 2, g = r & 3;
        int grow = g * HDIM + (cta * UPC + u);
        const float4* src = (const float4*)(W_hh + (size_t)grow * HDIM) + c * 2;
        float4 v0 = src[0], v1 = src[1];
        uint4 w;
        __half2* hp = (__half2*)&w;
        hp[0] = __floats2half2_rn(v0.x, v0.y); hp[1] = __floats2half2_rn(v0.z, v0.w);
        hp[2] = __floats2half2_rn(v1.x, v1.y); hp[3] = __floats2half2_rn(v1.z, v1.w);
        *(uint4*)(w_s + r * WSTRIDE + ((c ^ (r & 7)) << 4)) = w;
    }
    // ---- Prologue 2: overflow units (12,13) -> global fp16 buffer, plain row-major ----
    if (nu == UPC) {
        for (int idx = tid; idx < 8 * 256; idx += NTHREADS) {
            int rr = idx >> 8, c = idx & 255;
            int u = 12 + (rr >> 2), g = rr & 3;
            int grow = g * HDIM + (cta * UPC + u);
            const float4* src = (const float4*)(W_hh + (size_t)grow * HDIM) + c * 2;
            float4 v0 = src[0], v1 = src[1];
            uint4 w;
            __half2* hp = (__half2*)&w;
            hp[0] = __floats2half2_rn(v0.x, v0.y); hp[1] = __floats2half2_rn(v0.z, v0.w);
            hp[2] = __floats2half2_rn(v1.x, v1.y); hp[3] = __floats2half2_rn(v1.z, v1.w);
            *(uint4*)((char*)g_whh_l2 + ((size_t)(cta * 8 + rr)) * WSTRIDE + (c << 4)) = w;
        }
    }
    // ---- Prologue 3: A = W_ih@W_emb, fused bias ----
    for (int r = warp; r < nrows; r += NWARPS) {
        int u = r >> 2, g = r & 3;
        int grow = g * HDIM + (cta * UPC + u);
        const float* wr = W_ih + (size_t)grow * EDIM;
        float a0 = 0.f, a1 = 0.f, dd = 0.f;
        for (int k = lane; k < EDIM; k += 32) {
            float w = wr[k];
            a0 += w * W_emb[2 * k];
            a1 += w * W_emb[2 * k + 1];
            dd += w * b_emb[k];
        }
        #pragma unroll
        for (int off = 16; off; off >>= 1) {
            a0 += __shfl_xor_sync(0xffffffffu, a0, off);
            a1 += __shfl_xor_sync(0xffffffffu, a1, off);
            dd += __shfl_xor_sync(0xffffffffu, dd, off);
        }
        if (lane == 0) { A0[r] = a0; A1[r] = a1; DD[r] = dd + b_ih[grow] + b_hh[grow]; }
    }
    // ---- Prologue 4: init state ----
    float c_reg = 0.f, wo0 = 0.f, wo1 = 0.f;
    int   my_gu = -1;
    if (tid < nu) {
        my_gu = cta * UPC + tid;
        c_reg = c0[my_gu];
        g_h[0][my_gu] = h0[my_gu];
        wo0 = W_out[my_gu];
        wo1 = W_out[HDIM + my_gu];
    }
    {
        int idx = cta * NTHREADS + tid;
        if (idx < 2 * MAXT) g_rawacc[idx] = 0.f;
    }
    const float b_o0 = b_out[0], b_o1 = b_out[1];
    float loss = 0.f;
    if (tid == 0) { VW[0] = 1.f; VW[1] = 1.f; }
    __threadfence();
    grid_barrier();

    // lane-constant HMMA addressing (outside t loop)
    const int warp_t = warp >> 2;            // tile (0..2 for HMMA warps)
    const int warp_s = warp & 3;             // k-strip
    const int R0 = warp_t * 16;
    const int lrow = R0 + (lane & 15);
    const uint32_t a_rowbase = smem_u32 + OFF_W + (uint32_t)lrow * WSTRIDE;
    const int rx = lrow & 7;
    const int chalf = lane >> 4;             // chunk +0 (k 0-7) or +1 (k 8-15)
    const uint32_t b_base = smem_u32 + OFF_HS2 + (uint32_t)(warp_s * 1024 + 4 * (lane & 3));

    // =============== main recurrence ===============
    for (int t = 0; t < T; t++) {
        // Phase A: stage h (float + half), finish step t-1 bookkeeping
        {
            const float4* hb = (const float4*)(g_h[t & 1]);
            float4 hv = ldcg_f4(hb + tid);
            ((float4*)h_sf)[tid] = hv;
            __half2* h2p = (__half2*)h_s2;
            h2p[2 * tid]     = __floats2half2_rn(hv.x, hv.y);
            h2p[2 * tid + 1] = __floats2half2_rn(hv.z, hv.w);
        }
        if (t > 0 && tid == 0) {
            float r0 = ldcg_f(&g_rawacc[2 * (t - 1)])     + b_o0;
            float r1 = ldcg_f(&g_rawacc[2 * (t - 1) + 1]) + b_o1;
            float gt0 = gtruth[2 * (t - 1)], gt1 = gtruth[2 * (t - 1) + 1];
            int ug = use_gt[t - 1];
            VW[0] = (ug == 1) ? gt0 : r0;
            VW[1] = (ug == 1) ? gt1 : r1;
            if (cta == 0) {
                out[2 * (t - 1)] = r0; out[2 * (t - 1) + 1] = r1;
                float d0 = r0 - gt0, d1 = r1 - gt1;
                loss += 0.5f * (d0 * d0 + d1 * d1);
            }
        }
        __syncthreads();
        const float v0s = VW[0], v1s = VW[1];

        // Phase B: gates
        if (warp < 12) {
            if (warp_t * 4 < uh) {
                float c0a = 0.f, c1a = 0.f, c2a = 0.f, c3a = 0.f;
                float c0b = 0.f, c1b = 0.f, c2b = 0.f, c3b = 0.f;
                #pragma unroll 8
                for (int i = 0; i < 32; i++) {
                    int c = warp_s * 64 + 2 * i + chalf;
                    uint32_t a_addr = a_rowbase + (uint32_t)(((c ^ rx) << 4));
                    uint32_t a0, a1, a2, a3, b0, b1;
                    asm volatile("ldmatrix.sync.aligned.m8n8.x4.shared.b16 {%0,%1,%2,%3}, [%4];"
                                 : "=r"(a0), "=r"(a1), "=r"(a2), "=r"(a3) : "r"(a_addr));
                    asm volatile("ld.shared.u32 %0, [%1];" : "=r"(b0) : "r"(b_base + 32u * i));
                    asm volatile("ld.shared.u32 %0, [%1];" : "=r"(b1) : "r"(b_base + 32u * i + 16u));
                    if (i & 1) {
                        asm volatile(
                            "mma.sync.aligned.m16n8k16.row.col.f32.f16.f16.f32 "
                            "{%0,%1,%2,%3},{%4,%5,%6,%7},{%8,%9},{%0,%1,%2,%3};"
                            : "+f"(c0b), "+f"(c1b), "+f"(c2b), "+f"(c3b)
                            : "r"(a0), "r"(a1), "r"(a2), "r"(a3), "r"(b0), "r"(b1));
                    } else {
                        asm volatile(
                            "mma.sync.aligned.m16n8k16.row.col.f32.f16.f16.f32 "
                            "{%0,%1,%2,%3},{%4,%5,%6,%7},{%8,%9},{%0,%1,%2,%3};"
                            : "+f"(c0a), "+f"(c1a), "+f"(c2a), "+f"(c3a)
                            : "r"(a0), "r"(a1), "r"(a2), "r"(a3), "r"(b0), "r"(b1));
                    }
                }
                float v0 = c0a + c0b, v2 = c2a + c2b;
                if ((lane & 3) == 0) {
                    part[(R0 + (lane >> 2)) * 4 + warp_s]     = v0;
                    part[(R0 + (lane >> 2) + 8) * 4 + warp_s] = v2;
                }
            }
        } else if (nu == UPC) {
            // scalar path for units 12,13 (rows 48..55), weights from L2 fp16
            for (int j = 0; j < 2; j++) {
                int rr = (warp - 12) * 2 + j;            // 0..7
                const uint4* wrow = (const uint4*)(g_whh_l2 + ((size_t)(cta * 8 + rr)) * HDIM);
                const float4* h4 = (const float4*)h_sf;
                float a0 = 0.f, a1 = 0.f, a2 = 0.f, a3 = 0.f;
                #pragma unroll
                for (int i = 0; i < 8; i++) {
                    uint4 w8 = ldcg_u4(wrow + i * 32 + lane);
                    float4 hx = h4[(i * 32 + lane) * 2];
                    float4 hy = h4[(i * 32 + lane) * 2 + 1];
                    __half2* hw = (__half2*)&w8;
                    float2 f0 = __half22float2(hw[0]);
                    float2 f1 = __half22float2(hw[1]);
                    float2 f2 = __half22float2(hw[2]);
                    float2 f3 = __half22float2(hw[3]);
                    a0 = fmaf(f0.x, hx.x, a0); a1 = fmaf(f0.y, hx.y, a1);
                    a2 = fmaf(f1.x, hx.z, a2); a3 = fmaf(f1.y, hx.w, a3);
                    a0 = fmaf(f2.x, hy.x, a0); a1 = fmaf(f2.y, hy.y, a1);
                    a2 = fmaf(f3.x, hy.z, a2); a3 = fmaf(f3.y, hy.w, a3);
                }
                float acc = (a0 + a1) + (a2 + a3);
                #pragma unroll
                for (int off = 16; off; off >>= 1)
                    acc += __shfl_xor_sync(0xffffffffu, acc, off);
                if (lane == 0) {
                    int r = 48 + rr;
                    GA[r] = acc + A0[r] * v0s + A1[r] * v1s + DD[r];
                }
            }
        }
        __syncthreads();

        // reduce strip partials for HMMA rows
        if (tid < 4 * uh) {
            float g4 = part[tid * 4] + part[tid * 4 + 1] + part[tid * 4 + 2] + part[tid * 4 + 3];
            GA[tid] = g4 + A0[tid] * v0s + A1[tid] * v1s + DD[tid];
        }
        __syncthreads();

        // Phase C: LSTM cell (warp 0), W_out partials via shfl
        if (warp == 0) {
            float p0 = 0.f, p1 = 0.f;
            if (lane < nu) {
                float gi = GA[lane * 4], gf = GA[lane * 4 + 1];
                float gg = GA[lane * 4 + 2], go = GA[lane * 4 + 3];
                float si = sigf(gi), sf = sigf(gf), so = sigf(go);
                c_reg = sf * c_reg + si * tanhfast(gg);
                float hn = so * tanhfast(c_reg);
                g_h[(t + 1) & 1][my_gu] = hn;
                p0 = wo0 * hn; p1 = wo1 * hn;
            }
            #pragma unroll
            for (int off = 16; off; off >>= 1) {
                p0 += __shfl_xor_sync(0xffffffffu, p0, off);
                p1 += __shfl_xor_sync(0xffffffffu, p1, off);
            }
            if (lane == 0 && nu > 0) {
                atomicAdd(&g_rawacc[2 * t],     p0);
                atomicAdd(&g_rawacc[2 * t + 1], p1);
            }
        }
        grid_barrier();
    }

    // ---- final output + loss ----
    if (cta == 0 && tid == 0) {
        float r0 = ldcg_f(&g_rawacc[2 * (T - 1)])     + b_o0;
        float r1 = ldcg_f(&g_rawacc[2 * (T - 1) + 1]) + b_o1;
        out[2 * (T - 1)] = r0; out[2 * (T - 1) + 1] = r1;
        float gt0 = gtruth[2 * (T - 1)], gt1 = gtruth[2 * (T - 1) + 1];
        float d0 = r0 - gt0, d1 = r1 - gt1;
        loss += 0.5f * (d0 * d0 + d1 * d1);
        out[2 * T] = loss;
    }
}

// ---------------- launch ----------------
extern "C" void kernel_launch(void* const* d_in, const int* in_sizes, int n_in,
                              void* d_out, int out_size)
{
    (void)in_sizes; (void)out_size;
    const float* h0     = (const float*)d_in[0];
    const float* c0     = (const float*)d_in[1];
    const float* gtruth = (const float*)d_in[2];
    const int*   use_gt = (const int*)  d_in[3];
    const float* W_emb  = (const float*)d_in[4];
    const float* b_emb  = (const float*)d_in[5];
    const float* W_ih   = (const float*)d_in[6];
    const float* b_ih   = (const float*)d_in[7];
    const float* W_hh   = (const float*)d_in[8];
    const float* b_hh   = (const float*)d_in[9];
    const float* W_out  = (const float*)d_in[10];
    const float* b_out  = (const float*)d_in[11];
    const int*   olen   = (n_in > 12) ? (const int*)d_in[12] : nullptr;
    float* out = (float*)d_out;

    cudaFuncSetAttribute(lstm_decoder_kernel,
                         cudaFuncAttributeMaxDynamicSharedMemorySize, SMEM_TOTAL);
    lstm_decoder_kernel<<<NUM_CTAS, NTHREADS, SMEM_TOTAL>>>(
        h0, c0, gtruth, use_gt, W_emb, b_emb, W_ih, b_ih,
        W_hh, b_hh, W_out, b_out, olen, out);
}